// round 7
// baseline (speedup 1.0000x reference)
#include <cuda_runtime.h>
#include <cuda_fp16.h>
#include <cstdint>

#define BB 4
#define CC 512
#define TT 2048
#define TFF 4096
#define NGROUPS 32
#define P1 512
#define P2 1024
#define M12 1536
#define K2X 1024   /* 2*512  */
#define K23 4096   /* 2*2048 */

// ---------------- scratch (device globals: allocation-free) ----------------
__device__ double g_colmean[TFF];
__device__ int    g_cdf[TFF];
__device__ int    g_idx[TT];
__device__ __half g_W12s[(size_t)M12 * K2X];
__device__ __half g_W3s[(size_t)CC * K23];
__device__ float g_bias12[M12];
__device__ __half g_bX[(size_t)BB * TT * K2X];   // 17 MB
__device__ __half g_b3[(size_t)BB * TT * K23];   // 67 MB
__device__ float g_y12[(size_t)BB * M12 * TT];   // 50 MB
__device__ float g_y3[(size_t)BB * CC * TT];     // 16 MB
__device__ float g_mu[3][BB * NGROUPS];
__device__ float g_rstd[3][BB * NGROUPS];

// ---------------- PTX helpers ----------------------------------------------
__device__ __forceinline__ uint32_t smem_u32(const void* p) {
    uint32_t a;
    asm("{ .reg .u64 t; cvta.to.shared.u64 t, %1; cvt.u32.u64 %0, t; }"
        : "=r"(a) : "l"(p));
    return a;
}
__device__ __forceinline__ void ldsm4(uint32_t* r, uint32_t addr) {
    asm volatile("ldmatrix.sync.aligned.m8n8.x4.shared.b16 {%0,%1,%2,%3}, [%4];"
                 : "=r"(r[0]), "=r"(r[1]), "=r"(r[2]), "=r"(r[3]) : "r"(addr));
}
__device__ __forceinline__ void mma16816(float* c, const uint32_t* a, const uint32_t* b) {
    asm volatile("mma.sync.aligned.m16n8k16.row.col.f32.f16.f16.f32 "
                 "{%0,%1,%2,%3}, {%4,%5,%6,%7}, {%8,%9}, {%0,%1,%2,%3};"
                 : "+f"(c[0]), "+f"(c[1]), "+f"(c[2]), "+f"(c[3])
                 : "r"(a[0]), "r"(a[1]), "r"(a[2]), "r"(a[3]),
                   "r"(b[0]), "r"(b[1]));
}
__device__ __forceinline__ void cp16(uint32_t dst, const void* src) {
    asm volatile("cp.async.cg.shared.global [%0], [%1], 16;" :: "r"(dst), "l"(src));
}
#define CP_COMMIT() asm volatile("cp.async.commit_group;")
#define CP_WAIT2()  asm volatile("cp.async.wait_group 2;")

__device__ __forceinline__ void split2(float w, __half& hi, __half& lo) {
    hi = __float2half_rn(w);
    lo = __float2half_rn(w - __half2float(hi));
}

// ---------------- 0) prep: W2,W1 -> fp16 hi duplicated + bias concat --------
__global__ void prep_kernel(const float* __restrict__ W2, const float* __restrict__ W1,
                            const float* __restrict__ b2, const float* __restrict__ b1) {
    int bid = blockIdx.x;
    if (bid < 2048) {                       // W2: P2 x CC
        int i = bid * 256 + threadIdx.x;
        int m = i / CC, k = i % CC;
        __half hi = __float2half_rn(W2[i]);
        size_t base = (size_t)m * K2X;
        g_W12s[base + k] = hi; g_W12s[base + CC + k] = hi;
    } else if (bid < 3072) {                // W1: P1 x CC
        int i = (bid - 2048) * 256 + threadIdx.x;
        int m = i / CC, k = i % CC;
        __half hi = __float2half_rn(W1[i]);
        size_t base = (size_t)(P2 + m) * K2X;
        g_W12s[base + k] = hi; g_W12s[base + CC + k] = hi;
    } else {                                // bias concat
        int i = (bid - 3072) * 256 + threadIdx.x;
        if (i < P2) g_bias12[i] = b2[i];
        else if (i < M12) g_bias12[i] = b1[i - P2];
    }
}

// ---------------- W3 -> fp16 hi duplicated ----------------------------------
__global__ void splitw3_kernel(const float* __restrict__ W) {
    int i = blockIdx.x * blockDim.x + threadIdx.x;
    int m = i / 2048, k = i % 2048;
    __half hi = __float2half_rn(W[i]);
    size_t base = (size_t)m * K23;
    g_W3s[base + k] = hi; g_W3s[base + 2048 + k] = hi;
}

// ---------------- 1) column means of frame_level_feature[0] ----------------
__global__ void colmean_kernel(const float* __restrict__ frame) {
    int t = blockIdx.x * blockDim.x + threadIdx.x;
    if (t >= TFF) return;
    const float* p = frame + t;
    double s0 = 0.0, s1 = 0.0, s2 = 0.0, s3 = 0.0;
#pragma unroll 4
    for (int c = 0; c < CC; c += 4) {
        s0 += (double)p[(long)c * TFF];
        s1 += (double)p[(long)(c + 1) * TFF];
        s2 += (double)p[(long)(c + 2) * TFF];
        s3 += (double)p[(long)(c + 3) * TFF];
    }
    g_colmean[t] = ((s0 + s1) + (s2 + s3)) * (1.0 / CC);
}

// ---------------- 2) normalize + cumsum + cdf (fp64, one block) ------------
__global__ void cdf_kernel() {
    __shared__ double blocksum[256];
    __shared__ double s_tot;
    int tid = threadIdx.x;
    const int CH = TFF / 256;
    double loc[CH];
    double s = 0.0;
#pragma unroll
    for (int i = 0; i < CH; i++) { s += g_colmean[tid * CH + i]; loc[i] = s; }
    blocksum[tid] = s;
    __syncthreads();
    if (tid == 0) {
        double r = 0.0;
        for (int i = 0; i < 256; i++) { double v = blocksum[i]; blocksum[i] = r; r += v; }
        s_tot = r;
    }
    __syncthreads();
    double base = blocksum[tid];
    double f = (double)TT / s_tot;
#pragma unroll
    for (int i = 0; i < CH; i++) {
        int v = (int)((base + loc[i]) * f);
        if (v > TT - 1) v = TT - 1;
        g_cdf[tid * CH + i] = v;
    }
}

// ---------------- 3) idx = argmin_j |cdf[j] - i| ----------------------------
__global__ void idx_kernel() {
    __shared__ int scdf[TFF];
    for (int j = threadIdx.x; j < TFF; j += blockDim.x) scdf[j] = g_cdf[j];
    __syncthreads();
    int i = blockIdx.x * blockDim.x + threadIdx.x;
    if (i >= TT) return;
    int best = 1 << 30, bj = 0;
    for (int j = 0; j < TFF; j++) {
        int d = scdf[j] - i;
        d = d < 0 ? -d : d;
        if (d < best) { best = d; bj = j; }
    }
    g_idx[i] = bj;
}

// ---------------- 5) feature transpose-split: B' = [hi ; lo] ----------------
__global__ void splitx_kernel(const float* __restrict__ X) {
    __shared__ float tile[32][33];
    int b = blockIdx.z, c0 = blockIdx.y * 32, t0 = blockIdx.x * 32;
    int tx = threadIdx.x, ty = threadIdx.y;
    tile[ty][tx] = X[((long)b * CC + c0 + ty) * TT + t0 + tx];
    __syncthreads();
    float w = tile[tx][ty];
    int n = t0 + ty, k = c0 + tx;
    __half hi, lo; split2(w, hi, lo);
    __half* d = g_bX + ((size_t)b * TT + n) * K2X;
    d[k] = hi; d[512 + k] = lo;
}

// ---------------- 6) gather + transpose-split into g_b3 ---------------------
__global__ void gather_split_kernel(const float* __restrict__ frame) {
    __shared__ float tile[32][33];
    int b = blockIdx.z, c0 = blockIdx.y * 32, t0 = blockIdx.x * 32;
    int tx = threadIdx.x, ty = threadIdx.y;
    tile[ty][tx] = frame[((long)b * CC + c0 + ty) * TFF + g_idx[t0 + tx]];
    __syncthreads();
    float w = tile[tx][ty];
    int n = t0 + ty, k = c0 + tx;
    __half hi, lo; split2(w, hi, lo);
    __half* d = g_b3 + ((size_t)b * TT + n) * K23;
    d[k] = hi; d[2048 + k] = lo;
}

// ---------------- 7) GroupNorm stats ----------------------------------------
__global__ void gn_stats_kernel(const float* __restrict__ buf, long bstride,
                                int chpg, int stage) {
    int g = blockIdx.x, b = blockIdx.y;
    long L = (long)chpg * TT;
    const float* p = buf + (long)b * bstride + (long)g * L;
    double s = 0.0, s2 = 0.0;
    for (long i = (long)threadIdx.x * 4; i < L; i += (long)blockDim.x * 4) {
        float4 v = *reinterpret_cast<const float4*>(p + i);
        s  += (double)v.x + (double)v.y + (double)v.z + (double)v.w;
        s2 += (double)v.x * v.x + (double)v.y * v.y + (double)v.z * v.z + (double)v.w * v.w;
    }
    __shared__ double sh[256], sh2[256];
    sh[threadIdx.x] = s; sh2[threadIdx.x] = s2;
    __syncthreads();
    for (int off = 128; off > 0; off >>= 1) {
        if (threadIdx.x < off) {
            sh[threadIdx.x]  += sh[threadIdx.x + off];
            sh2[threadIdx.x] += sh2[threadIdx.x + off];
        }
        __syncthreads();
    }
    if (threadIdx.x == 0) {
        double mean = sh[0] / (double)L;
        double var  = sh2[0] / (double)L - mean * mean;
        g_mu[stage][b * NGROUPS + g]   = (float)mean;
        g_rstd[stage][b * NGROUPS + g] = (float)rsqrt(var + 1e-5);
    }
}

// ------- 8) GN+ReLU, write optional fp32 out AND transposed fp16 split ------
__global__ void gn_split_kernel(const float* __restrict__ y, long ybs,
                                int chpg, int stage, int chanoff,
                                const float* __restrict__ gamma,
                                const float* __restrict__ beta,
                                float* __restrict__ outf, long obs) {
    __shared__ float tile[32][33];
    int b = blockIdx.z, c0 = blockIdx.y * 32, t0 = blockIdx.x * 32;
    int tx = threadIdx.x, ty = threadIdx.y;
    int c = c0 + ty;
    float mu = g_mu[stage][b * NGROUPS + c / chpg];
    float rs = g_rstd[stage][b * NGROUPS + c / chpg];
    float ga = gamma[c] * rs, bt = beta[c] - mu * ga;
    float v = fmaxf(fmaf(y[(long)b * ybs + (long)c * TT + t0 + tx], ga, bt), 0.f);
    if (outf) outf[(long)b * obs + (long)c * TT + t0 + tx] = v;
    tile[ty][tx] = v;
    __syncthreads();
    float w = tile[tx][ty];
    int n = t0 + ty, k = chanoff + c0 + tx;
    __half hi, lo; split2(w, hi, lo);
    __half* d = g_b3 + ((size_t)b * TT + n) * K23;
    d[k] = hi; d[2048 + k] = lo;
}

// ---------------- 9) final GN+ReLU (fp32 out only) ---------------------------
__global__ void gn_out_kernel(const float* __restrict__ in, long in_bs,
                              float* __restrict__ out, long out_bs,
                              const float* __restrict__ gamma,
                              const float* __restrict__ beta,
                              int chpg, int stage) {
    int c = blockIdx.x, b = blockIdx.y;
    int g = c / chpg;
    float mu = g_mu[stage][b * NGROUPS + g];
    float rs = g_rstd[stage][b * NGROUPS + g];
    float ga = gamma[c] * rs, bt = beta[c] - mu * ga;
    const float* ip = in + (long)b * in_bs + (long)c * TT;
    float* op = out + (long)b * out_bs + (long)c * TT;
    for (int i = threadIdx.x * 4; i < TT; i += blockDim.x * 4) {
        float4 v = *reinterpret_cast<const float4*>(ip + i);
        v.x = fmaxf(fmaf(v.x, ga, bt), 0.f);
        v.y = fmaxf(fmaf(v.y, ga, bt), 0.f);
        v.z = fmaxf(fmaf(v.z, ga, bt), 0.f);
        v.w = fmaxf(fmaf(v.w, ga, bt), 0.f);
        *reinterpret_cast<float4*>(op + i) = v;
    }
}

// ---------------- 10) HMMA fp16 GEMM, 128x256 tile, cp.async 4-stage --------
// A' [M, K2] row-major, B' [B][N=2048, K2] row-major (both K-contiguous).
// C [B][M, 2048] fp32. Block tile 128x256, BK=32, 8 warps of 64x64.
#define SPITCH 40                          /* fp16 elems per smem row (80 B) */
#define SP2 (SPITCH * 2)
#define A_BYTES (128 * SP2)                /* 10240 */
#define B_BYTES (256 * SP2)                /* 20480 */
#define STAGE_BYTES (A_BYTES + B_BYTES)    /* 30720 */
#define NSTAGE 4

__global__ __launch_bounds__(256, 1)
void wmma_gemm_kernel(const __half* __restrict__ A,
                      const __half* __restrict__ Bm,
                      const float* __restrict__ bias,
                      float* __restrict__ Cm,
                      int K2, long bsB, long bsC) {
    extern __shared__ char smem[];
    uint32_t sb = smem_u32(smem);
    int tid = threadIdx.x, lane = tid & 31, wid = tid >> 5;
    int bx = blockIdx.x, by = blockIdx.y, bz = blockIdx.z;
    int wm = (wid & 1) * 64, wn = (wid >> 1) * 64;

    const __half* Ab = A + (long)(by * 128) * K2;
    const __half* Bb = Bm + (long)bz * bsB + (long)(bx * 256) * K2;

    uint32_t a_lane = (lane & 15) * SP2 + (lane >> 4) * 16;
    uint32_t b_lane = ((lane & 7) + ((lane >> 4) & 1) * 8) * SP2
                    + ((lane >> 3) & 1) * 16;

    float acc[4][8][4];
#pragma unroll
    for (int i = 0; i < 4; i++)
#pragma unroll
        for (int j = 0; j < 8; j++)
#pragma unroll
            for (int r = 0; r < 4; r++) acc[i][j][r] = 0.f;

    // stage loader: A 512 chunks (2/thread), B 1024 chunks (4/thread)
    auto load_stage = [&](int s, int k0) {
        uint32_t sa = sb + s * STAGE_BYTES;
#pragma unroll
        for (int i = 0; i < 2; i++) {
            int id = tid + 256 * i;
            int row = id >> 2, q = id & 3;
            cp16(sa + row * SP2 + q * 16, Ab + (long)row * K2 + k0 + q * 8);
        }
        uint32_t sbb = sa + A_BYTES;
#pragma unroll
        for (int i = 0; i < 4; i++) {
            int id = tid + 256 * i;
            int row = id >> 2, q = id & 3;
            cp16(sbb + row * SP2 + q * 16, Bb + (long)row * K2 + k0 + q * 8);
        }
    };

    int NT = K2 >> 5;
    load_stage(0, 0);  CP_COMMIT();
    load_stage(1, 32); CP_COMMIT();
    load_stage(2, 64); CP_COMMIT();

    for (int t = 0; t < NT; t++) {
        int cur = t & 3;
        CP_WAIT2();
        __syncthreads();
        if (t + 3 < NT) load_stage((t + 3) & 3, (t + 3) * 32);
        CP_COMMIT();

        uint32_t abase = sb + cur * STAGE_BYTES + a_lane + wm * SP2;
        uint32_t bbase = sb + cur * STAGE_BYTES + A_BYTES + b_lane + wn * SP2;
#pragma unroll
        for (int ks = 0; ks < 2; ks++) {
            uint32_t a[4][4], b[8][2];
#pragma unroll
            for (int fm = 0; fm < 4; fm++)
                ldsm4(a[fm], abase + fm * 16 * SP2 + ks * 32);
#pragma unroll
            for (int j = 0; j < 4; j++) {
                uint32_t r[4];
                ldsm4(r, bbase + j * 16 * SP2 + ks * 32);
                b[j * 2][0] = r[0]; b[j * 2][1] = r[1];
                b[j * 2 + 1][0] = r[2]; b[j * 2 + 1][1] = r[3];
            }
#pragma unroll
            for (int fm = 0; fm < 4; fm++)
#pragma unroll
                for (int fn = 0; fn < 8; fn++)
                    mma16816(acc[fm][fn], a[fm], b[fn]);
        }
    }

    int rowg = lane >> 2, colg = (lane & 3) * 2;
    float* Cb = Cm + (long)bz * bsC;
#pragma unroll
    for (int fm = 0; fm < 4; fm++) {
        int m0 = by * 128 + wm + fm * 16 + rowg;
        float bv0 = bias[m0], bv1 = bias[m0 + 8];
#pragma unroll
        for (int fn = 0; fn < 8; fn++) {
            int n0 = bx * 256 + wn + fn * 8 + colg;
            float2 v0 = { acc[fm][fn][0] + bv0, acc[fm][fn][1] + bv0 };
            float2 v1 = { acc[fm][fn][2] + bv1, acc[fm][fn][3] + bv1 };
            *reinterpret_cast<float2*>(Cb + (long)m0 * TT + n0) = v0;
            *reinterpret_cast<float2*>(Cb + (long)(m0 + 8) * TT + n0) = v1;
        }
    }
}

// ---------------- launch -----------------------------------------------------
extern "C" void kernel_launch(void* const* d_in, const int* in_sizes, int n_in,
                              void* d_out, int out_size) {
    const float* feature = (const float*)d_in[0];
    const float* frame   = (const float*)d_in[1];
    const float* W1  = (const float*)d_in[2];
    const float* b1  = (const float*)d_in[3];
    const float* g1  = (const float*)d_in[4];
    const float* be1 = (const float*)d_in[5];
    const float* W2  = (const float*)d_in[6];
    const float* b2  = (const float*)d_in[7];
    const float* g2  = (const float*)d_in[8];
    const float* be2 = (const float*)d_in[9];
    const float* W3  = (const float*)d_in[10];
    const float* b3  = (const float*)d_in[11];
    const float* g3  = (const float*)d_in[12];
    const float* be3 = (const float*)d_in[13];

    float* out_mixed = (float*)d_out;
    float* out_feat  = out_mixed + (long)BB * CC * TT;

    __half *w12s, *w3s, *bX, *b3buf;
    float *y12, *y3, *bias12;
    cudaGetSymbolAddress((void**)&w12s, g_W12s);
    cudaGetSymbolAddress((void**)&w3s, g_W3s);
    cudaGetSymbolAddress((void**)&bX,  g_bX);
    cudaGetSymbolAddress((void**)&b3buf, g_b3);
    cudaGetSymbolAddress((void**)&y12, g_y12);
    cudaGetSymbolAddress((void**)&y3, g_y3);
    cudaGetSymbolAddress((void**)&bias12, g_bias12);

    cudaFuncSetAttribute(wmma_gemm_kernel,
                         cudaFuncAttributeMaxDynamicSharedMemorySize,
                         NSTAGE * STAGE_BYTES);

    // 0: W2+W1 fp16 + bias concat
    prep_kernel<<<3072 + 6, 256>>>(W2, W1, b2, b1);
    // 1: feature transpose-split
    splitx_kernel<<<dim3(TT / 32, CC / 32, BB), dim3(32, 32)>>>(feature);
    // 2: colmean (independent)
    colmean_kernel<<<TFF / 256, 256>>>(frame);
    // 3: stacked GEMM1+2  (profiled slot)
    wmma_gemm_kernel<<<dim3(TT / 256, M12 / 128, BB), 256, NSTAGE * STAGE_BYTES>>>(
        w12s, bX, bias12, y12, K2X, (long)TT * K2X, (long)M12 * TT);

    // W3 fp16 + resample path
    splitw3_kernel<<<(CC * 2048) / 256, 256>>>(W3);
    cdf_kernel<<<1, 256>>>();
    idx_kernel<<<TT / 256, 256>>>();
    gather_split_kernel<<<dim3(TT / 32, CC / 32, BB), dim3(32, 32)>>>(frame);

    // GroupNorm + ReLU; feat -> fp32 out + fp16 split; fm_short -> fp16 split
    gn_stats_kernel<<<dim3(NGROUPS, BB), 256>>>(y12, (long)M12 * TT, P2 / NGROUPS, 1);
    gn_stats_kernel<<<dim3(NGROUPS, BB), 256>>>(y12 + (long)P2 * TT, (long)M12 * TT,
                                                P1 / NGROUPS, 0);
    gn_split_kernel<<<dim3(TT / 32, P2 / 32, BB), dim3(32, 32)>>>(
        y12, (long)M12 * TT, P2 / NGROUPS, 1, 512, g2, be2, out_feat, (long)P2 * TT);
    gn_split_kernel<<<dim3(TT / 32, P1 / 32, BB), dim3(32, 32)>>>(
        y12 + (long)P2 * TT, (long)M12 * TT, P1 / NGROUPS, 0, 1536, g1, be1,
        (float*)0, 0);

    // GEMM3 over concatenated (split) input, then final GN+ReLU
    wmma_gemm_kernel<<<dim3(TT / 256, CC / 128, BB), 256, NSTAGE * STAGE_BYTES>>>(
        w3s, b3buf, b3, y3, K23, (long)TT * K23, (long)CC * TT);
    gn_stats_kernel<<<dim3(NGROUPS, BB), 256>>>(y3, (long)CC * TT, CC / NGROUPS, 2);
    gn_out_kernel<<<dim3(CC, BB), 256>>>(
        y3, (long)CC * TT, out_mixed, (long)CC * TT, g3, be3, CC / NGROUPS, 2);
}